// round 14
// baseline (speedup 1.0000x reference)
#include <cuda_runtime.h>

// NECTAR binning — 64x4 warp bands, 2 px/thread, explicit 2-stage row pipeline
// within a 64-reg / 8-CTA-per-SM envelope.
// logits [16,4,512,512] f32, val_freqs [4,9,15] f32 -> out [16,4,512,512] f32.

#define H_DIM 512
#define W_DIM 512
#define HW    (H_DIM * W_DIM)
#define NTH   128                    // 4 warps; each warp = 64x4 band
#define BAND  4

struct R2d { float2 a, b, c, d; float h0, h1, h2, h3; };

__device__ __forceinline__ unsigned int argmax_w(float l0, float l1, float l2, float l3,
                                                 float& m) {
    m = l0; unsigned int w = 1u;
    if (l1 > m) { m = l1; w = 1u << 8;  }
    if (l2 > m) { m = l2; w = 1u << 16; }
    if (l3 > m) { m = l3; w = 1u << 24; }
    return w;
}

// unconditional row load (caller clamps gy); halo floats only on enabled lanes
__device__ __forceinline__ R2d load_row(const float* __restrict__ pb, int gy,
                                        bool haloLd, int haloDx) {
    R2d v;
    const float* pr = pb + (unsigned)gy * W_DIM;
    v.a = *(const float2*)(pr);
    v.b = *(const float2*)(pr + HW);
    v.c = *(const float2*)(pr + 2 * HW);
    v.d = *(const float2*)(pr + 3 * HW);
    v.h0 = v.h1 = v.h2 = v.h3 = 0.0f;
    if (haloLd) {
        const float* hp = pr + haloDx;
        v.h0 = __ldg(hp);
        v.h1 = __ldg(hp + HW);
        v.h2 = __ldg(hp + 2 * HW);
        v.h3 = __ldg(hp + 3 * HW);
    }
    return v;
}

__device__ __forceinline__ void proc_cw(const R2d& v, bool haloOk,
                                        unsigned int cw[2], unsigned int& hw_) {
    float m;
    cw[0] = argmax_w(v.a.x, v.b.x, v.c.x, v.d.x, m);
    cw[1] = argmax_w(v.a.y, v.b.y, v.c.y, v.d.y, m);
    const unsigned int h = argmax_w(v.h0, v.h1, v.h2, v.h3, m);
    hw_ = haloOk ? h : 0u;
}

__device__ __forceinline__ void proc_full(const R2d& v, bool haloOk,
                                          unsigned int cw[2], unsigned int binw[2],
                                          unsigned int& hw_) {
    const float p0[2] = {v.a.x, v.a.y};
    const float p1[2] = {v.b.x, v.b.y};
    const float p2[2] = {v.c.x, v.c.y};
    const float p3[2] = {v.d.x, v.d.y};
    const float bw = 1.0f / 15.0f;

    #pragma unroll
    for (int j = 0; j < 2; j++) {
        const float l0 = p0[j], l1 = p1[j], l2 = p2[j], l3 = p3[j];
        float m;
        cw[j] = argmax_w(l0, l1, l2, l3, m);

        // fast path (no max-subtract; mathematically identical softmax)
        const float e0 = __expf(l0);
        const float e1 = __expf(l1);
        const float e2 = __expf(l2);
        const float e3 = __expf(l3);
        const float s  = e0 + e1 + e2 + e3;
        const float tt = __fdividef(15.0f, s);
        const float u0 = e0 * tt, u1 = e1 * tt, u2 = e2 * tt, u3 = e3 * tt;
        int b0 = (int)u0, b1 = (int)u1, b2 = (int)u2, b3 = (int)u3;

        const float g = 1e-4f;   // fast-path |u| error bound ~2.3e-5 -> 4x margin
        const float d0 = fminf(fabsf(u0 - rintf(u0)), fabsf(u1 - rintf(u1)));
        const float d1 = fminf(fabsf(u2 - rintf(u2)), fabsf(u3 - rintf(u3)));
        if (fminf(d0, d1) < g) {
            // exact path: bit-validated reference formula
            const float a0 = expf(l0 - m);
            const float a1 = expf(l1 - m);
            const float a2 = expf(l2 - m);
            const float a3 = expf(l3 - m);
            const float as = a0 + a1 + a2 + a3;
            const float at = (1.0f / as) / bw;
            b0 = (int)(a0 * at);
            b1 = (int)(a1 * at);
            b2 = (int)(a2 * at);
            b3 = (int)(a3 * at);
        }
        b0 = b0 > 14 ? 14 : b0;
        b1 = b1 > 14 ? 14 : b1;
        b2 = b2 > 14 ? 14 : b2;
        b3 = b3 > 14 ? 14 : b3;
        const unsigned int t0 = __byte_perm((unsigned)b0, (unsigned)b1, 0x0040);
        const unsigned int t1 = __byte_perm((unsigned)b2, (unsigned)b3, 0x0040);
        binw[j] = __byte_perm(t0, t1, 0x5410);
    }
    float m;
    const unsigned int h = argmax_w(v.h0, v.h1, v.h2, v.h3, m);
    hw_ = haloOk ? h : 0u;
}

__device__ __forceinline__ void hwin(const unsigned int cw[2], unsigned int hw_,
                                     int lane, unsigned int W3[2]) {
    unsigned int prev = __shfl_up_sync(0xffffffffu, cw[1], 1);
    if (lane == 0)  prev = hw_;
    unsigned int nxt  = __shfl_down_sync(0xffffffffu, cw[0], 1);
    if (lane == 31) nxt = hw_;
    const unsigned int c01 = cw[0] + cw[1];
    W3[0] = prev + c01;
    W3[1] = c01  + nxt;
}

__device__ __forceinline__ void emit_row(float* __restrict__ po,
                                         const unsigned int S[2], const unsigned int W3[2],
                                         const unsigned int binsp[2],
                                         const float* __restrict__ s_vf) {
    float o0[2], o1[2], o2[2], o3[2];
    #pragma unroll
    for (int j = 0; j < 2; j++) {
        const unsigned int acc = S[j] + W3[j];
        const unsigned int idx = acc * 15u + binsp[j];   // per-byte 15*cnt+bin <= 134
        const float f0 = s_vf[        ( idx         & 0xFFu)];
        const float f1 = s_vf[135u + ((idx >> 8)    & 0xFFu)];
        const float f2 = s_vf[270u + ((idx >> 16)   & 0xFFu)];
        const float f3 = s_vf[405u + ( idx >> 24          )];
        float s = f0 + f1 + f2 + f3;
        s = (s == 0.0f) ? 1.0f : s;
        const float inv = __fdividef(1.0f, s);
        o0[j] = f0 * inv; o1[j] = f1 * inv; o2[j] = f2 * inv; o3[j] = f3 * inv;
    }
    __stcs((float2*)(po),          make_float2(o0[0], o0[1]));
    __stcs((float2*)(po + HW),     make_float2(o1[0], o1[1]));
    __stcs((float2*)(po + 2 * HW), make_float2(o2[0], o2[1]));
    __stcs((float2*)(po + 3 * HW), make_float2(o3[0], o3[1]));
}

__global__ __launch_bounds__(NTH, 8)     // 64-reg cap -> 8 CTAs/SM, ILP headroom
void nectar_binning_kernel(const float* __restrict__ logits,
                           const float* __restrict__ val_freqs,
                           float* __restrict__ out)
{
    __shared__ float s_vf[540];
    const int tid  = threadIdx.x;
    const int lane = tid & 31;
    const int wrp  = tid >> 5;

    for (int i = tid; i < 540; i += NTH) s_vf[i] = val_freqs[i];
    __syncthreads();

    const int x0    = blockIdx.x * 64;
    const int ybase = (blockIdx.y * 4 + wrp) * BAND;
    const unsigned int boff = blockIdx.z * 4u * HW;

    const float* pb = logits + boff + (unsigned)x0 + 2u * (unsigned)lane;
    float*       ob = out    + boff + (unsigned)x0 + 2u * (unsigned)lane;

    const bool edgeLane = (lane == 0) | (lane == 31);
    const bool haloOk   = edgeLane & ((lane == 0) ? (x0 > 0) : (x0 + 64 < W_DIM));
    const int  haloDx   = (lane == 0) ? -1 : 2;

    const bool vT = (ybase > 0);
    const bool vB = (ybase + BAND < H_DIM);
    const int  gyT = vT ? (ybase - 1) : 0;              // clamped
    const int  gyB = vB ? (ybase + BAND) : (H_DIM - 1); // clamped

    unsigned int cw[2], binw[2], W3p[2], W3[2], S[2], binsp[2], hw_;

    // ---- pipeline prologue: rows -1 and 0 in flight ----
    R2d rA = load_row(pb, gyT,   haloOk, haloDx);   // row -1 (clamped)
    R2d rB = load_row(pb, ybase, haloOk, haloDx);   // row 0

    // proc row -1 (cw only)
    proc_cw(rA, haloOk & vT, cw, hw_);
    if (!vT) { cw[0] = 0u; cw[1] = 0u; }
    hwin(cw, hw_, lane, W3p);

    rA = load_row(pb, ybase + 1, haloOk, haloDx);   // row 1 in flight

    // proc row 0
    proc_full(rB, haloOk, cw, binw, hw_);
    hwin(cw, hw_, lane, W3);
    #pragma unroll
    for (int j = 0; j < 2; j++) {
        S[j] = W3p[j] + (W3[j] - cw[j]);
        W3p[j] = W3[j];
        binsp[j] = binw[j];
    }

    rB = load_row(pb, ybase + 2, haloOk, haloDx);   // row 2 in flight

    // proc row 1, emit row 0
    proc_full(rA, haloOk, cw, binw, hw_);
    hwin(cw, hw_, lane, W3);
    emit_row(ob + (unsigned)ybase * W_DIM, S, W3, binsp, s_vf);
    #pragma unroll
    for (int j = 0; j < 2; j++) {
        S[j] = W3p[j] + (W3[j] - cw[j]);
        W3p[j] = W3[j];
        binsp[j] = binw[j];
    }

    rA = load_row(pb, ybase + 3, haloOk, haloDx);   // row 3 in flight

    // proc row 2, emit row 1
    proc_full(rB, haloOk, cw, binw, hw_);
    hwin(cw, hw_, lane, W3);
    emit_row(ob + (unsigned)(ybase + 1) * W_DIM, S, W3, binsp, s_vf);
    #pragma unroll
    for (int j = 0; j < 2; j++) {
        S[j] = W3p[j] + (W3[j] - cw[j]);
        W3p[j] = W3[j];
        binsp[j] = binw[j];
    }

    rB = load_row(pb, gyB, haloOk, haloDx);         // row 4 (clamped) in flight

    // proc row 3, emit row 2
    proc_full(rA, haloOk, cw, binw, hw_);
    hwin(cw, hw_, lane, W3);
    emit_row(ob + (unsigned)(ybase + 2) * W_DIM, S, W3, binsp, s_vf);
    #pragma unroll
    for (int j = 0; j < 2; j++) {
        S[j] = W3p[j] + (W3[j] - cw[j]);
        binsp[j] = binw[j];
    }

    // proc row 4 (cw only), emit row 3
    proc_cw(rB, haloOk & vB, cw, hw_);
    if (!vB) { cw[0] = 0u; cw[1] = 0u; }
    hwin(cw, hw_, lane, W3);
    emit_row(ob + (unsigned)(ybase + 3) * W_DIM, S, W3, binsp, s_vf);
}

extern "C" void kernel_launch(void* const* d_in, const int* in_sizes, int n_in,
                              void* d_out, int out_size)
{
    const float* logits    = (const float*)d_in[0];
    const float* val_freqs = (const float*)d_in[1];
    float*       out       = (float*)d_out;

    const int B = in_sizes[0] / (4 * HW);            // 16

    dim3 grid(W_DIM / 64, H_DIM / (4 * BAND), B);    // 8 x 32 x 16 = 4096 CTAs
    nectar_binning_kernel<<<grid, NTH>>>(logits, val_freqs, out);
}

// round 15
// speedup vs baseline: 1.0082x; 1.0082x over previous
#include <cuda_runtime.h>

// NECTAR binning — 64x16 warp bands, 2 px/thread, 2-stage ping-pong pipeline,
// 2-warp CTAs. logits [16,4,512,512] f32, val_freqs [4,9,15] -> out.

#define H_DIM 512
#define W_DIM 512
#define HW    (H_DIM * W_DIM)
#define NTH   64                     // 2 warps; each warp = 64x16 band
#define BAND  16

struct R2d { float2 a, b, c, d; float h0, h1, h2, h3; };

__device__ __forceinline__ unsigned int argmax_w(float l0, float l1, float l2, float l3,
                                                 float& m) {
    m = l0; unsigned int w = 1u;
    if (l1 > m) { m = l1; w = 1u << 8;  }
    if (l2 > m) { m = l2; w = 1u << 16; }
    if (l3 > m) { m = l3; w = 1u << 24; }
    return w;
}

__device__ __forceinline__ R2d load_row(const float* __restrict__ pb, int gy,
                                        bool haloLd, int haloDx) {
    R2d v;
    const float* pr = pb + (unsigned)gy * W_DIM;
    v.a = *(const float2*)(pr);
    v.b = *(const float2*)(pr + HW);
    v.c = *(const float2*)(pr + 2 * HW);
    v.d = *(const float2*)(pr + 3 * HW);
    v.h0 = v.h1 = v.h2 = v.h3 = 0.0f;
    if (haloLd) {
        const float* hp = pr + haloDx;
        v.h0 = __ldg(hp);
        v.h1 = __ldg(hp + HW);
        v.h2 = __ldg(hp + 2 * HW);
        v.h3 = __ldg(hp + 3 * HW);
    }
    return v;
}

__device__ __forceinline__ void proc_cw(const R2d& v, bool haloOk,
                                        unsigned int cw[2], unsigned int& hw_) {
    float m;
    cw[0] = argmax_w(v.a.x, v.b.x, v.c.x, v.d.x, m);
    cw[1] = argmax_w(v.a.y, v.b.y, v.c.y, v.d.y, m);
    const unsigned int h = argmax_w(v.h0, v.h1, v.h2, v.h3, m);
    hw_ = haloOk ? h : 0u;
}

__device__ __forceinline__ void proc_full(const R2d& v, bool haloOk,
                                          unsigned int cw[2], unsigned int binw[2],
                                          unsigned int& hw_) {
    const float p0[2] = {v.a.x, v.a.y};
    const float p1[2] = {v.b.x, v.b.y};
    const float p2[2] = {v.c.x, v.c.y};
    const float p3[2] = {v.d.x, v.d.y};
    const float bw = 1.0f / 15.0f;

    #pragma unroll
    for (int j = 0; j < 2; j++) {
        const float l0 = p0[j], l1 = p1[j], l2 = p2[j], l3 = p3[j];
        float m;
        cw[j] = argmax_w(l0, l1, l2, l3, m);

        // fast path (no max-subtract; mathematically identical softmax)
        const float e0 = __expf(l0);
        const float e1 = __expf(l1);
        const float e2 = __expf(l2);
        const float e3 = __expf(l3);
        const float s  = e0 + e1 + e2 + e3;
        const float tt = __fdividef(15.0f, s);
        const float u0 = e0 * tt, u1 = e1 * tt, u2 = e2 * tt, u3 = e3 * tt;
        int b0 = (int)u0, b1 = (int)u1, b2 = (int)u2, b3 = (int)u3;

        const float g = 1e-4f;   // fast-path |u| error bound ~2.3e-5 -> 4x margin
        const float d0 = fminf(fabsf(u0 - rintf(u0)), fabsf(u1 - rintf(u1)));
        const float d1 = fminf(fabsf(u2 - rintf(u2)), fabsf(u3 - rintf(u3)));
        if (fminf(d0, d1) < g) {
            // exact path: bit-validated reference formula
            const float a0 = expf(l0 - m);
            const float a1 = expf(l1 - m);
            const float a2 = expf(l2 - m);
            const float a3 = expf(l3 - m);
            const float as = a0 + a1 + a2 + a3;
            const float at = (1.0f / as) / bw;
            b0 = (int)(a0 * at);
            b1 = (int)(a1 * at);
            b2 = (int)(a2 * at);
            b3 = (int)(a3 * at);
        }
        b0 = b0 > 14 ? 14 : b0;
        b1 = b1 > 14 ? 14 : b1;
        b2 = b2 > 14 ? 14 : b2;
        b3 = b3 > 14 ? 14 : b3;
        const unsigned int t0 = __byte_perm((unsigned)b0, (unsigned)b1, 0x0040);
        const unsigned int t1 = __byte_perm((unsigned)b2, (unsigned)b3, 0x0040);
        binw[j] = __byte_perm(t0, t1, 0x5410);
    }
    float m;
    const unsigned int h = argmax_w(v.h0, v.h1, v.h2, v.h3, m);
    hw_ = haloOk ? h : 0u;
}

__device__ __forceinline__ void hwin(const unsigned int cw[2], unsigned int hw_,
                                     int lane, unsigned int W3[2]) {
    unsigned int prev = __shfl_up_sync(0xffffffffu, cw[1], 1);
    if (lane == 0)  prev = hw_;
    unsigned int nxt  = __shfl_down_sync(0xffffffffu, cw[0], 1);
    if (lane == 31) nxt = hw_;
    const unsigned int c01 = cw[0] + cw[1];
    W3[0] = prev + c01;
    W3[1] = c01  + nxt;
}

__device__ __forceinline__ void emit_row(float* __restrict__ po,
                                         const unsigned int S[2], const unsigned int W3[2],
                                         const unsigned int binsp[2],
                                         const float* __restrict__ s_vf) {
    float o0[2], o1[2], o2[2], o3[2];
    #pragma unroll
    for (int j = 0; j < 2; j++) {
        const unsigned int acc = S[j] + W3[j];
        const unsigned int idx = acc * 15u + binsp[j];   // per-byte 15*cnt+bin <= 134
        const float f0 = s_vf[        __byte_perm(idx, 0u, 0x4440)];
        const float f1 = s_vf[135u +  __byte_perm(idx, 0u, 0x4441)];
        const float f2 = s_vf[270u +  __byte_perm(idx, 0u, 0x4442)];
        const float f3 = s_vf[405u + (idx >> 24)];
        float s = f0 + f1 + f2 + f3;
        s = (s == 0.0f) ? 1.0f : s;
        const float inv = __fdividef(1.0f, s);
        o0[j] = f0 * inv; o1[j] = f1 * inv; o2[j] = f2 * inv; o3[j] = f3 * inv;
    }
    __stcs((float2*)(po),          make_float2(o0[0], o0[1]));
    __stcs((float2*)(po + HW),     make_float2(o1[0], o1[1]));
    __stcs((float2*)(po + 2 * HW), make_float2(o2[0], o2[1]));
    __stcs((float2*)(po + 3 * HW), make_float2(o3[0], o3[1]));
}

__global__ __launch_bounds__(NTH, 16)    // 64-reg cap, up to 32 warps/SM
void nectar_binning_kernel(const float* __restrict__ logits,
                           const float* __restrict__ val_freqs,
                           float* __restrict__ out)
{
    __shared__ float s_vf[540];
    const int tid  = threadIdx.x;
    const int lane = tid & 31;
    const int wrp  = tid >> 5;

    for (int i = tid; i < 540; i += NTH) s_vf[i] = val_freqs[i];
    __syncthreads();

    const int x0    = blockIdx.x * 64;
    const int ybase = (blockIdx.y * 2 + wrp) * BAND;
    const unsigned int boff = blockIdx.z * 4u * HW;

    const float* pb = logits + boff + (unsigned)x0 + 2u * (unsigned)lane;
    float*       ob = out    + boff + (unsigned)x0 + 2u * (unsigned)lane;

    const bool edgeLane = (lane == 0) | (lane == 31);
    const bool haloOk   = edgeLane & ((lane == 0) ? (x0 > 0) : (x0 + 64 < W_DIM));
    const int  haloDx   = (lane == 0) ? -1 : 2;

    const bool vT = (ybase > 0);
    const bool vB = (ybase + BAND < H_DIM);
    const int  gyT = vT ? (ybase - 1) : 0;              // clamped
    const int  gyB = vB ? (ybase + BAND) : (H_DIM - 1); // clamped

    unsigned int cw[2], binw[2], W3p[2], W3[2], S[2], binsp[2], hw_;

    // ---- prologue: rows -1 and 0 in flight ----
    R2d cur = load_row(pb, gyT,   haloOk, haloDx);
    R2d nxt = load_row(pb, ybase, haloOk, haloDx);

    proc_cw(cur, haloOk & vT, cw, hw_);
    if (!vT) { cw[0] = 0u; cw[1] = 0u; }
    hwin(cw, hw_, lane, W3p);
    cur = nxt;

    nxt = load_row(pb, ybase + 1, haloOk, haloDx);
    proc_full(cur, haloOk, cw, binw, hw_);
    hwin(cw, hw_, lane, W3);
    #pragma unroll
    for (int j = 0; j < 2; j++) {
        S[j] = W3p[j] + (W3[j] - cw[j]);
        W3p[j] = W3[j];
        binsp[j] = binw[j];
    }
    cur = nxt;

    // ---- middle rows 1..BAND-2: rolled ping-pong pipeline (unroll 2) ----
    #pragma unroll 2
    for (int r = 1; r <= BAND - 2; ++r) {
        nxt = load_row(pb, ybase + r + 1, haloOk, haloDx);
        proc_full(cur, haloOk, cw, binw, hw_);
        hwin(cw, hw_, lane, W3);
        emit_row(ob + (unsigned)(ybase + r - 1) * W_DIM, S, W3, binsp, s_vf);
        #pragma unroll
        for (int j = 0; j < 2; j++) {
            S[j] = W3p[j] + (W3[j] - cw[j]);
            W3p[j] = W3[j];
            binsp[j] = binw[j];
        }
        cur = nxt;
    }

    // ---- row BAND-1: prefetch bottom halo, process, emit BAND-2 ----
    nxt = load_row(pb, gyB, haloOk, haloDx);
    proc_full(cur, haloOk, cw, binw, hw_);
    hwin(cw, hw_, lane, W3);
    emit_row(ob + (unsigned)(ybase + BAND - 2) * W_DIM, S, W3, binsp, s_vf);
    #pragma unroll
    for (int j = 0; j < 2; j++) {
        S[j] = W3p[j] + (W3[j] - cw[j]);
        binsp[j] = binw[j];
    }

    // ---- bottom halo row (cw only), emit row BAND-1 ----
    proc_cw(nxt, haloOk & vB, cw, hw_);
    if (!vB) { cw[0] = 0u; cw[1] = 0u; }
    hwin(cw, hw_, lane, W3);
    emit_row(ob + (unsigned)(ybase + BAND - 1) * W_DIM, S, W3, binsp, s_vf);
}

extern "C" void kernel_launch(void* const* d_in, const int* in_sizes, int n_in,
                              void* d_out, int out_size)
{
    const float* logits    = (const float*)d_in[0];
    const float* val_freqs = (const float*)d_in[1];
    float*       out       = (float*)d_out;

    const int B = in_sizes[0] / (4 * HW);            // 16

    dim3 grid(W_DIM / 64, H_DIM / (2 * BAND), B);    // 8 x 16 x 16 = 2048 CTAs
    nectar_binning_kernel<<<grid, NTH>>>(logits, val_freqs, out);
}

// round 16
// speedup vs baseline: 1.0685x; 1.0598x over previous
#include <cuda_runtime.h>

// NECTAR binning — 64x8 warp bands, 2 px/thread, explicit ping-pong pipeline.
// Midpoint of parallelism (8192 warps) vs halo amortization (1.25x loads).
// logits [16,4,512,512] f32, val_freqs [4,9,15] f32 -> out [16,4,512,512] f32.

#define H_DIM 512
#define W_DIM 512
#define HW    (H_DIM * W_DIM)
#define NTH   128                    // 4 warps; each warp = 64x8 band
#define BAND  8

struct R2d { float2 a, b, c, d; float h0, h1, h2, h3; };

__device__ __forceinline__ unsigned int argmax_w(float l0, float l1, float l2, float l3,
                                                 float& m) {
    m = l0; unsigned int w = 1u;
    if (l1 > m) { m = l1; w = 1u << 8;  }
    if (l2 > m) { m = l2; w = 1u << 16; }
    if (l3 > m) { m = l3; w = 1u << 24; }
    return w;
}

__device__ __forceinline__ R2d load_row(const float* __restrict__ pb, int gy,
                                        bool haloLd, int haloDx) {
    R2d v;
    const float* pr = pb + (unsigned)gy * W_DIM;
    v.a = *(const float2*)(pr);
    v.b = *(const float2*)(pr + HW);
    v.c = *(const float2*)(pr + 2 * HW);
    v.d = *(const float2*)(pr + 3 * HW);
    v.h0 = v.h1 = v.h2 = v.h3 = 0.0f;
    if (haloLd) {
        const float* hp = pr + haloDx;
        v.h0 = __ldg(hp);
        v.h1 = __ldg(hp + HW);
        v.h2 = __ldg(hp + 2 * HW);
        v.h3 = __ldg(hp + 3 * HW);
    }
    return v;
}

__device__ __forceinline__ void proc_cw(const R2d& v, bool haloOk,
                                        unsigned int cw[2], unsigned int& hw_) {
    float m;
    cw[0] = argmax_w(v.a.x, v.b.x, v.c.x, v.d.x, m);
    cw[1] = argmax_w(v.a.y, v.b.y, v.c.y, v.d.y, m);
    const unsigned int h = argmax_w(v.h0, v.h1, v.h2, v.h3, m);
    hw_ = haloOk ? h : 0u;
}

__device__ __forceinline__ void proc_full(const R2d& v, bool haloOk,
                                          unsigned int cw[2], unsigned int binw[2],
                                          unsigned int& hw_) {
    const float p0[2] = {v.a.x, v.a.y};
    const float p1[2] = {v.b.x, v.b.y};
    const float p2[2] = {v.c.x, v.c.y};
    const float p3[2] = {v.d.x, v.d.y};
    const float bw = 1.0f / 15.0f;

    #pragma unroll
    for (int j = 0; j < 2; j++) {
        const float l0 = p0[j], l1 = p1[j], l2 = p2[j], l3 = p3[j];
        float m;
        cw[j] = argmax_w(l0, l1, l2, l3, m);

        // fast path (no max-subtract; mathematically identical softmax)
        const float e0 = __expf(l0);
        const float e1 = __expf(l1);
        const float e2 = __expf(l2);
        const float e3 = __expf(l3);
        const float s  = e0 + e1 + e2 + e3;
        const float tt = __fdividef(15.0f, s);
        const float u0 = e0 * tt, u1 = e1 * tt, u2 = e2 * tt, u3 = e3 * tt;
        int b0 = (int)u0, b1 = (int)u1, b2 = (int)u2, b3 = (int)u3;

        const float g = 1e-4f;   // fast-path |u| error bound ~2.3e-5 -> 4x margin
        const float d0 = fminf(fabsf(u0 - rintf(u0)), fabsf(u1 - rintf(u1)));
        const float d1 = fminf(fabsf(u2 - rintf(u2)), fabsf(u3 - rintf(u3)));
        if (fminf(d0, d1) < g) {
            // exact path: bit-validated reference formula
            const float a0 = expf(l0 - m);
            const float a1 = expf(l1 - m);
            const float a2 = expf(l2 - m);
            const float a3 = expf(l3 - m);
            const float as = a0 + a1 + a2 + a3;
            const float at = (1.0f / as) / bw;
            b0 = (int)(a0 * at);
            b1 = (int)(a1 * at);
            b2 = (int)(a2 * at);
            b3 = (int)(a3 * at);
        }
        b0 = b0 > 14 ? 14 : b0;
        b1 = b1 > 14 ? 14 : b1;
        b2 = b2 > 14 ? 14 : b2;
        b3 = b3 > 14 ? 14 : b3;
        const unsigned int t0 = __byte_perm((unsigned)b0, (unsigned)b1, 0x0040);
        const unsigned int t1 = __byte_perm((unsigned)b2, (unsigned)b3, 0x0040);
        binw[j] = __byte_perm(t0, t1, 0x5410);
    }
    float m;
    const unsigned int h = argmax_w(v.h0, v.h1, v.h2, v.h3, m);
    hw_ = haloOk ? h : 0u;
}

__device__ __forceinline__ void hwin(const unsigned int cw[2], unsigned int hw_,
                                     int lane, unsigned int W3[2]) {
    unsigned int prev = __shfl_up_sync(0xffffffffu, cw[1], 1);
    if (lane == 0)  prev = hw_;
    unsigned int nxt  = __shfl_down_sync(0xffffffffu, cw[0], 1);
    if (lane == 31) nxt = hw_;
    const unsigned int c01 = cw[0] + cw[1];
    W3[0] = prev + c01;
    W3[1] = c01  + nxt;
}

__device__ __forceinline__ void emit_row(float* __restrict__ po,
                                         const unsigned int S[2], const unsigned int W3[2],
                                         const unsigned int binsp[2],
                                         const float* __restrict__ s_vf) {
    float o0[2], o1[2], o2[2], o3[2];
    #pragma unroll
    for (int j = 0; j < 2; j++) {
        const unsigned int acc = S[j] + W3[j];
        const unsigned int idx = acc * 15u + binsp[j];   // per-byte 15*cnt+bin <= 134
        const float f0 = s_vf[        __byte_perm(idx, 0u, 0x4440)];
        const float f1 = s_vf[135u +  __byte_perm(idx, 0u, 0x4441)];
        const float f2 = s_vf[270u +  __byte_perm(idx, 0u, 0x4442)];
        const float f3 = s_vf[405u + (idx >> 24)];
        float s = f0 + f1 + f2 + f3;
        s = (s == 0.0f) ? 1.0f : s;
        const float inv = __fdividef(1.0f, s);
        o0[j] = f0 * inv; o1[j] = f1 * inv; o2[j] = f2 * inv; o3[j] = f3 * inv;
    }
    __stcs((float2*)(po),          make_float2(o0[0], o0[1]));
    __stcs((float2*)(po + HW),     make_float2(o1[0], o1[1]));
    __stcs((float2*)(po + 2 * HW), make_float2(o2[0], o2[1]));
    __stcs((float2*)(po + 3 * HW), make_float2(o3[0], o3[1]));
}

__global__ __launch_bounds__(NTH, 8)     // 64-reg cap -> 8 CTAs/SM
void nectar_binning_kernel(const float* __restrict__ logits,
                           const float* __restrict__ val_freqs,
                           float* __restrict__ out)
{
    __shared__ float s_vf[540];
    const int tid  = threadIdx.x;
    const int lane = tid & 31;
    const int wrp  = tid >> 5;

    for (int i = tid; i < 540; i += NTH) s_vf[i] = val_freqs[i];
    __syncthreads();

    const int x0    = blockIdx.x * 64;
    const int ybase = (blockIdx.y * 4 + wrp) * BAND;
    const unsigned int boff = blockIdx.z * 4u * HW;

    const float* pb = logits + boff + (unsigned)x0 + 2u * (unsigned)lane;
    float*       ob = out    + boff + (unsigned)x0 + 2u * (unsigned)lane;

    const bool edgeLane = (lane == 0) | (lane == 31);
    const bool haloOk   = edgeLane & ((lane == 0) ? (x0 > 0) : (x0 + 64 < W_DIM));
    const int  haloDx   = (lane == 0) ? -1 : 2;

    const bool vT = (ybase > 0);
    const bool vB = (ybase + BAND < H_DIM);
    const int  gyT = vT ? (ybase - 1) : 0;              // clamped
    const int  gyB = vB ? (ybase + BAND) : (H_DIM - 1); // clamped

    unsigned int cw[2], binw[2], W3p[2], W3[2], S[2], binsp[2], hw_;

    // ---- prologue: rows -1 and 0 in flight ----
    R2d cur = load_row(pb, gyT,   haloOk, haloDx);
    R2d nxt = load_row(pb, ybase, haloOk, haloDx);

    proc_cw(cur, haloOk & vT, cw, hw_);
    if (!vT) { cw[0] = 0u; cw[1] = 0u; }
    hwin(cw, hw_, lane, W3p);
    cur = nxt;

    nxt = load_row(pb, ybase + 1, haloOk, haloDx);
    proc_full(cur, haloOk, cw, binw, hw_);
    hwin(cw, hw_, lane, W3);
    #pragma unroll
    for (int j = 0; j < 2; j++) {
        S[j] = W3p[j] + (W3[j] - cw[j]);
        W3p[j] = W3[j];
        binsp[j] = binw[j];
    }
    cur = nxt;

    // ---- middle rows 1..BAND-2: rolled ping-pong pipeline (unroll 2) ----
    #pragma unroll 2
    for (int r = 1; r <= BAND - 2; ++r) {
        nxt = load_row(pb, ybase + r + 1, haloOk, haloDx);
        proc_full(cur, haloOk, cw, binw, hw_);
        hwin(cw, hw_, lane, W3);
        emit_row(ob + (unsigned)(ybase + r - 1) * W_DIM, S, W3, binsp, s_vf);
        #pragma unroll
        for (int j = 0; j < 2; j++) {
            S[j] = W3p[j] + (W3[j] - cw[j]);
            W3p[j] = W3[j];
            binsp[j] = binw[j];
        }
        cur = nxt;
    }

    // ---- row BAND-1: prefetch bottom halo, process, emit BAND-2 ----
    nxt = load_row(pb, gyB, haloOk, haloDx);
    proc_full(cur, haloOk, cw, binw, hw_);
    hwin(cw, hw_, lane, W3);
    emit_row(ob + (unsigned)(ybase + BAND - 2) * W_DIM, S, W3, binsp, s_vf);
    #pragma unroll
    for (int j = 0; j < 2; j++) {
        S[j] = W3p[j] + (W3[j] - cw[j]);
        binsp[j] = binw[j];
    }

    // ---- bottom halo row (cw only), emit row BAND-1 ----
    proc_cw(nxt, haloOk & vB, cw, hw_);
    if (!vB) { cw[0] = 0u; cw[1] = 0u; }
    hwin(cw, hw_, lane, W3);
    emit_row(ob + (unsigned)(ybase + BAND - 1) * W_DIM, S, W3, binsp, s_vf);
}

extern "C" void kernel_launch(void* const* d_in, const int* in_sizes, int n_in,
                              void* d_out, int out_size)
{
    const float* logits    = (const float*)d_in[0];
    const float* val_freqs = (const float*)d_in[1];
    float*       out       = (float*)d_out;

    const int B = in_sizes[0] / (4 * HW);            // 16

    dim3 grid(W_DIM / 64, H_DIM / (4 * BAND), B);    // 8 x 16 x 16 = 2048 CTAs
    nectar_binning_kernel<<<grid, NTH>>>(logits, val_freqs, out);
}